// round 1
// baseline (speedup 1.0000x reference)
#include <cuda_runtime.h>
#include <math.h>

// ---------------- problem constants ----------------
#define BB 2
#define TT 2048
#define DD 1024
#define MM (BB*TT)          // 4096 token rows
#define INNER 2048
#define DSTATE 64
#define EE 4
#define HID 4096

// ---------------- scratch (device globals; no allocation allowed) ----------
__device__ float g_h   [MM*DD];        // rmsnorm1 output
__device__ float g_xz  [MM*2*INNER];   // in_proj output (x_main | gate)
__device__ float g_xm  [MM*INNER];     // conv+silu output
__device__ float g_dt  [MM*DSTATE];
__device__ float g_Bm  [MM*DSTATE];
__device__ float g_Cm  [MM*DSTATE];
__device__ float g_y   [MM*DSTATE];    // scan output, layernormed in-place
__device__ float g_y2  [MM*INNER];
__device__ float g_x1  [MM*DD];        // post-mixer residual
__device__ float g_h2  [MM*DD];        // rmsnorm2 output
__device__ float g_wf  [MM*EE];        // per-token expert combine weights
__device__ float g_hid [MM*HID];       // MoE hidden (reused across experts)

// ---------------- helpers ----------------
__device__ __forceinline__ float sigmoidf_(float x){ return 1.f/(1.f+expf(-x)); }

// ---------------- rmsnorm: one block per row of DD ----------------
__global__ void rmsnorm_kernel(const float* __restrict__ x, const float* __restrict__ w,
                               float* __restrict__ out)
{
    __shared__ float red[256];
    int row = blockIdx.x, tid = threadIdx.x;
    const float* xr = x + (size_t)row*DD;
    float s = 0.f;
    #pragma unroll
    for (int i = 0; i < DD/256; i++){ float v = xr[tid + i*256]; s += v*v; }
    red[tid] = s; __syncthreads();
    for (int off = 128; off > 0; off >>= 1){ if (tid < off) red[tid] += red[tid+off]; __syncthreads(); }
    float nr = rsqrtf(red[0]/(float)DD + 1e-6f);
    float* orow = out + (size_t)row*DD;
    #pragma unroll
    for (int i = 0; i < DD/256; i++){ int c = tid + i*256; orow[c] = xr[c]*nr*w[c]; }
}

// ---------------- generic 128x128x8 SGEMM with epilogues ----------------
// EPI: 0 = bias only
//      1 = s2i: (acc+bias + ep2[col]*ep1[row*N+col]) * sigmoid(ep3[row*ep_stride+col])
//      2 = residual: acc+bias + ep1[row*ep_stride+col]
//      3 = gelu(acc+bias) (exact, erf)
//      4 = moe accumulate: C[row,col] += ep1[row*4] * (acc+bias)
template<int EPI>
__global__ void __launch_bounds__(256) gemm128(
    const float* __restrict__ A, const float* __restrict__ B,
    float* __restrict__ C, int M, int N, int K,
    const float* __restrict__ bias,
    const float* __restrict__ ep1, const float* __restrict__ ep2,
    const float* __restrict__ ep3, int ep_stride)
{
    __shared__ float As[8][128];
    __shared__ float Bs[8][128];
    int tid = threadIdx.x;
    int tx = tid & 15, ty = tid >> 4;
    int rowBase = blockIdx.y * 128;
    int colBase = blockIdx.x * 128;
    int aRow = tid >> 1, aCol = (tid & 1)*4;
    int bRow = tid >> 5, bCol = (tid & 31)*4;
    const float* Aptr = A + (size_t)(rowBase + aRow)*K + aCol;
    const float* Bptr = B + (size_t)bRow*N + colBase + bCol;
    float acc[8][8];
    #pragma unroll
    for (int i=0;i<8;i++) 
        #pragma unroll
        for (int j=0;j<8;j++) acc[i][j]=0.f;

    for (int k0 = 0; k0 < K; k0 += 8) {
        float4 av = *reinterpret_cast<const float4*>(Aptr + k0);
        float4 bv = *reinterpret_cast<const float4*>(Bptr + (size_t)k0*N);
        As[aCol+0][aRow]=av.x; As[aCol+1][aRow]=av.y; As[aCol+2][aRow]=av.z; As[aCol+3][aRow]=av.w;
        *reinterpret_cast<float4*>(&Bs[bRow][bCol]) = bv;
        __syncthreads();
        #pragma unroll
        for (int k = 0; k < 8; k++) {
            float a[8], b[8];
            #pragma unroll
            for (int i=0;i<8;i++) a[i] = As[k][ty*8+i];
            #pragma unroll
            for (int j=0;j<8;j++) b[j] = Bs[k][tx*8+j];
            #pragma unroll
            for (int i=0;i<8;i++)
                #pragma unroll
                for (int j=0;j<8;j++) acc[i][j] = fmaf(a[i], b[j], acc[i][j]);
        }
        __syncthreads();
    }

    #pragma unroll
    for (int i=0;i<8;i++){
        int row = rowBase + ty*8 + i;
        #pragma unroll
        for (int j=0;j<8;j++){
            int col = colBase + tx*8 + j;
            float v = acc[i][j] + bias[col];
            if (EPI == 1) {
                v += ep2[col]*ep1[(size_t)row*N + col];
                v *= sigmoidf_(ep3[(size_t)row*ep_stride + col]);
            } else if (EPI == 2) {
                v += ep1[(size_t)row*ep_stride + col];
            } else if (EPI == 3) {
                v = 0.5f*v*(1.f + erff(v*0.70710678118654752f));
            }
            if (EPI == 4) C[(size_t)row*N + col] += ep1[(size_t)row*4]*v;
            else          C[(size_t)row*N + col] = v;
        }
    }
}

// ---------------- causal depthwise conv (K=3) + bias + silu ----------------
__global__ void conv_silu_kernel(const float* __restrict__ xz,
                                 const float* __restrict__ cw,
                                 const float* __restrict__ cb,
                                 float* __restrict__ xm)
{
    int idx = blockIdx.x*blockDim.x + threadIdx.x;
    if (idx >= MM*INNER) return;
    int c  = idx & (INNER-1);
    int rt = idx >> 11;              // INNER = 2048 = 2^11
    int t  = rt & (TT-1);
    const float* w = cw + c*3;
    float v = w[2]*xz[(size_t)rt*(2*INNER) + c];
    if (t >= 1) v += w[1]*xz[(size_t)(rt-1)*(2*INNER) + c];
    if (t >= 2) v += w[0]*xz[(size_t)(rt-2)*(2*INNER) + c];
    v += cb[c];
    xm[(size_t)rt*INNER + c] = v * sigmoidf_(v);   // silu
}

// ---------------- dt/B/C projections: [M,2048]@[2048,64], blockIdx.y picks matrix
__global__ void __launch_bounds__(256) proj_kernel(
    const float* __restrict__ X,
    const float* __restrict__ Wdt, const float* __restrict__ Wb, const float* __restrict__ Wc,
    const float* __restrict__ bdt, const float* __restrict__ bb, const float* __restrict__ bc,
    float* __restrict__ odt, float* __restrict__ oB, float* __restrict__ oC)
{
    const int Kp = INNER;
    int mat = blockIdx.y;
    const float* W    = (mat==0)? Wdt : (mat==1)? Wb : Wc;
    const float* bias = (mat==0)? bdt : (mat==1)? bb : bc;
    float* out        = (mat==0)? odt : (mat==1)? oB : oC;
    __shared__ float Xs[32][64];
    __shared__ float Ws[32][64];
    int tid = threadIdx.x;
    int tx = tid & 15, ty = tid >> 4;
    int rowBase = blockIdx.x * 64;
    float acc[4][4];
    #pragma unroll
    for (int i=0;i<4;i++) 
        #pragma unroll
        for (int j=0;j<4;j++) acc[i][j]=0.f;

    for (int k0 = 0; k0 < Kp; k0 += 32) {
        #pragma unroll
        for (int h=0; h<2; h++){
            int r = (tid>>3) + h*32;
            int c = (tid&7)*4;
            float4 v = *reinterpret_cast<const float4*>(&X[(size_t)(rowBase+r)*Kp + k0 + c]);
            Xs[c+0][r]=v.x; Xs[c+1][r]=v.y; Xs[c+2][r]=v.z; Xs[c+3][r]=v.w;
        }
        #pragma unroll
        for (int h=0; h<2; h++){
            int r = (tid>>4) + h*16;
            int c = (tid&15)*4;
            *reinterpret_cast<float4*>(&Ws[r][c]) =
                *reinterpret_cast<const float4*>(&W[(size_t)(k0+r)*64 + c]);
        }
        __syncthreads();
        #pragma unroll
        for (int k=0;k<32;k++){
            float a[4], b[4];
            #pragma unroll
            for (int i=0;i<4;i++) a[i]=Xs[k][ty*4+i];
            #pragma unroll
            for (int j=0;j<4;j++) b[j]=Ws[k][tx*4+j];
            #pragma unroll
            for (int i=0;i<4;i++)
                #pragma unroll
                for (int j=0;j<4;j++) acc[i][j]=fmaf(a[i],b[j],acc[i][j]);
        }
        __syncthreads();
    }
    #pragma unroll
    for (int i=0;i<4;i++){
        int row = rowBase + ty*4 + i;
        #pragma unroll
        for (int j=0;j<4;j++){
            int col = tx*4 + j;
            float v = acc[i][j] + bias[col];
            if (mat == 0) v = sigmoidf_(v);
            out[(size_t)row*64 + col] = v;
        }
    }
}

// ---------------- selective-scan: 128 independent (b,s) channels, length 2048
// state_t = (1-dt)*state + dt*B ; y = C*state.  Affine-pair parallel scan.
__global__ void scan_kernel(const float* __restrict__ dt, const float* __restrict__ Bm,
                            const float* __restrict__ Cm, float* __restrict__ y)
{
    __shared__ float sA[256], sU[256];
    int bs = blockIdx.x;           // 0..127
    int b = bs >> 6, s = bs & 63;
    int tid = threadIdx.x;
    size_t base = (size_t)b*TT*DSTATE + s;
    float a_l[8], u_l[8], c_l[8];
    float A = 1.f, U = 0.f;
    #pragma unroll
    for (int i=0;i<8;i++){
        int t = tid*8 + i;
        size_t off = base + (size_t)t*DSTATE;
        float d  = dt[off];
        float bb = Bm[off];
        c_l[i] = Cm[off];
        float a = 1.f - d, u = d*bb;
        a_l[i]=a; u_l[i]=u;
        U = a*U + u;  A = a*A;
    }
    sA[tid]=A; sU[tid]=U; __syncthreads();
    for (int off=1; off<256; off<<=1){
        float pa=1.f, pu=0.f;
        if (tid >= off){ pa = sA[tid-off]; pu = sU[tid-off]; }
        __syncthreads();
        if (tid >= off){ U = A*pu + U; A = A*pa; }
        sA[tid]=A; sU[tid]=U; __syncthreads();
    }
    float state = (tid > 0) ? sU[tid-1] : 0.f;
    #pragma unroll
    for (int i=0;i<8;i++){
        state = a_l[i]*state + u_l[i];
        int t = tid*8 + i;
        y[base + (size_t)t*DSTATE] = c_l[i]*state;
    }
}

// ---------------- layernorm over dim 64, in-place, no affine ----------------
__global__ void ln64_kernel(float* __restrict__ y)
{
    __shared__ float red[64];
    __shared__ float mu_s, var_s;
    int row = blockIdx.x, tid = threadIdx.x;
    float v = y[(size_t)row*64 + tid];
    red[tid] = v; __syncthreads();
    for (int off=32; off>0; off>>=1){ if (tid<off) red[tid]+=red[tid+off]; __syncthreads(); }
    if (tid==0) mu_s = red[0]/64.f;
    __syncthreads();
    float d = v - mu_s;
    red[tid] = d*d; __syncthreads();
    for (int off=32; off>0; off>>=1){ if (tid<off) red[tid]+=red[tid+off]; __syncthreads(); }
    if (tid==0) var_s = red[0]/64.f;
    __syncthreads();
    y[(size_t)row*64 + tid] = d * rsqrtf(var_s + 1e-5f);
}

// ---------------- gating: logits, top-2, softmax -> dense weights ----------
__global__ void gate_kernel(const float* __restrict__ h2, const float* __restrict__ gw,
                            const float* __restrict__ gb, float* __restrict__ wf)
{
    __shared__ float red[4][128];
    int row = blockIdx.x, tid = threadIdx.x;
    float p[4] = {0.f,0.f,0.f,0.f};
    const float* hr = h2 + (size_t)row*DD;
    for (int d = tid; d < DD; d += 128){
        float hv = hr[d];
        #pragma unroll
        for (int e=0;e<4;e++) p[e] = fmaf(hv, gw[d*4+e], p[e]);
    }
    #pragma unroll
    for (int e=0;e<4;e++) red[e][tid]=p[e];
    __syncthreads();
    for (int off=64; off>0; off>>=1){
        if (tid < off) { 
            #pragma unroll
            for (int e=0;e<4;e++) red[e][tid]+=red[e][tid+off]; 
        }
        __syncthreads();
    }
    if (tid == 0){
        float l[4];
        #pragma unroll
        for (int e=0;e<4;e++) l[e] = red[e][0] + gb[e];
        int i0 = 0;
        #pragma unroll
        for (int e=1;e<4;e++) if (l[e] > l[i0]) i0 = e;
        int i1 = -1;
        #pragma unroll
        for (int e=0;e<4;e++) if (e != i0 && (i1 < 0 || l[e] > l[i1])) i1 = e;
        float ex = expf(l[i1] - l[i0]);
        float p0 = 1.f/(1.f+ex), p1 = ex/(1.f+ex);
        float w[4] = {0.f,0.f,0.f,0.f};
        w[i0]=p0; w[i1]=p1;
        #pragma unroll
        for (int e=0;e<4;e++) wf[(size_t)row*4+e]=w[e];
    }
}

// ---------------- copy x1 -> d_out (float4) ----------------
__global__ void copy4_kernel(const float* __restrict__ src, float* __restrict__ dst, int n4)
{
    int i = blockIdx.x*blockDim.x + threadIdx.x;
    if (i < n4) reinterpret_cast<float4*>(dst)[i] = reinterpret_cast<const float4*>(src)[i];
}

// ---------------- host launcher ----------------
static float* sym(const void* s){ void* p=nullptr; cudaGetSymbolAddress(&p, s); return (float*)p; }

extern "C" void kernel_launch(void* const* d_in, const int* in_sizes, int n_in,
                              void* d_out, int out_size)
{
    const float* x        = (const float*)d_in[0];
    const float* norm1_w  = (const float*)d_in[1];
    const float* norm2_w  = (const float*)d_in[2];
    const float* in_proj_w= (const float*)d_in[3];
    const float* in_proj_b= (const float*)d_in[4];
    const float* conv_w   = (const float*)d_in[5];
    const float* conv_b   = (const float*)d_in[6];
    const float* dt_w     = (const float*)d_in[7];
    const float* dt_b     = (const float*)d_in[8];
    const float* bp_w     = (const float*)d_in[9];
    const float* bp_b     = (const float*)d_in[10];
    const float* cp_w     = (const float*)d_in[11];
    const float* cp_b     = (const float*)d_in[12];
    const float* s2i_w    = (const float*)d_in[13];
    const float* s2i_b    = (const float*)d_in[14];
    const float* D_param  = (const float*)d_in[15];
    const float* out_w    = (const float*)d_in[16];
    const float* out_b    = (const float*)d_in[17];
    const float* gate_w   = (const float*)d_in[18];
    const float* gate_b   = (const float*)d_in[19];
    const float* e_w1     = (const float*)d_in[20];
    const float* e_b1     = (const float*)d_in[21];
    const float* e_w2     = (const float*)d_in[22];
    const float* e_b2     = (const float*)d_in[23];
    float* out = (float*)d_out;

    float* p_h   = sym(g_h);
    float* p_xz  = sym(g_xz);
    float* p_xm  = sym(g_xm);
    float* p_dt  = sym(g_dt);
    float* p_Bm  = sym(g_Bm);
    float* p_Cm  = sym(g_Cm);
    float* p_y   = sym(g_y);
    float* p_y2  = sym(g_y2);
    float* p_x1  = sym(g_x1);
    float* p_h2  = sym(g_h2);
    float* p_wf  = sym(g_wf);
    float* p_hid = sym(g_hid);

    // 1. rmsnorm(x, norm1_w) -> h
    rmsnorm_kernel<<<MM, 256>>>(x, norm1_w, p_h);

    // 2. xz = h @ in_proj_w + b   [4096, 4096]
    gemm128<0><<<dim3(2*INNER/128, MM/128), 256>>>(p_h, in_proj_w, p_xz,
        MM, 2*INNER, DD, in_proj_b, nullptr, nullptr, nullptr, 0);

    // 3. causal depthwise conv + silu -> x_main  [4096, 2048]
    conv_silu_kernel<<<(MM*INNER)/256, 256>>>(p_xz, conv_w, conv_b, p_xm);

    // 4. dt (sigmoid), Bm, Cm  [4096, 64] each
    proj_kernel<<<dim3(MM/64, 3), 256>>>(p_xm, dt_w, bp_w, cp_w, dt_b, bp_b, cp_b,
                                         p_dt, p_Bm, p_Cm);

    // 5. selective scan -> y  [4096, 64]
    scan_kernel<<<BB*DSTATE, 256>>>(p_dt, p_Bm, p_Cm, p_y);

    // 6. layernorm over 64 (in place)
    ln64_kernel<<<MM, 64>>>(p_y);

    // 7. y2 = (y @ s2i_w + b + D*x_main) * sigmoid(gate)  [4096, 2048]
    gemm128<1><<<dim3(INNER/128, MM/128), 256>>>(p_y, s2i_w, p_y2,
        MM, INNER, DSTATE, s2i_b, p_xm, D_param, p_xz + INNER, 2*INNER);

    // 8. x1 = x + (y2 @ out_w + b)   [4096, 1024]
    gemm128<2><<<dim3(DD/128, MM/128), 256>>>(p_y2, out_w, p_x1,
        MM, DD, INNER, out_b, x, nullptr, nullptr, DD);

    // 9. rmsnorm(x1, norm2_w) -> h2
    rmsnorm_kernel<<<MM, 256>>>(p_x1, norm2_w, p_h2);

    // 10. gating -> wf [4096, 4]
    gate_kernel<<<MM, 128>>>(p_h2, gate_w, gate_b, p_wf);

    // 11. out = x1 (then accumulate experts)
    copy4_kernel<<<(MM*DD/4 + 255)/256, 256>>>(p_x1, out, MM*DD/4);

    // 12. per-expert: hid = gelu(h2 @ w1 + b1); out += w * (hid @ w2 + b2)
    for (int e = 0; e < EE; e++){
        gemm128<3><<<dim3(HID/128, MM/128), 256>>>(p_h2, e_w1 + (size_t)e*DD*HID, p_hid,
            MM, HID, DD, e_b1 + (size_t)e*HID, nullptr, nullptr, nullptr, 0);
        gemm128<4><<<dim3(DD/128, MM/128), 256>>>(p_hid, e_w2 + (size_t)e*HID*DD, out,
            MM, DD, HID, e_b2 + (size_t)e*DD, p_wf + e, nullptr, nullptr, 0);
    }
}

// round 2
// speedup vs baseline: 1.5155x; 1.5155x over previous
#include <cuda_runtime.h>
#include <math.h>

// ---------------- problem constants ----------------
#define BB 2
#define TT 2048
#define DD 1024
#define MM (BB*TT)          // 4096 token rows
#define INNER 2048
#define DSTATE 64
#define EE 4
#define HID 4096

// ---------------- scratch (device globals; no allocation allowed) ----------
__device__ float g_h   [MM*DD];
__device__ float g_xz  [MM*2*INNER];
__device__ float g_xm  [MM*INNER];
__device__ float g_dt  [MM*DSTATE];
__device__ float g_Bm  [MM*DSTATE];
__device__ float g_Cm  [MM*DSTATE];
__device__ float g_y   [MM*DSTATE];
__device__ float g_y2  [MM*INNER];
__device__ float g_x1  [MM*DD];
__device__ float g_h2  [MM*DD];
__device__ float g_wf  [MM*EE];
__device__ float g_hid [MM*HID];

// ---------------- helpers ----------------
__device__ __forceinline__ float sigmoidf_(float x){ return 1.f/(1.f+expf(-x)); }
__device__ __forceinline__ unsigned f2tf(float x){
    unsigned r; asm("cvt.rna.tf32.f32 %0, %1;" : "=r"(r) : "f"(x)); return r;
}

// ---------------- rmsnorm ----------------
__global__ void rmsnorm_kernel(const float* __restrict__ x, const float* __restrict__ w,
                               float* __restrict__ out)
{
    __shared__ float red[256];
    int row = blockIdx.x, tid = threadIdx.x;
    const float* xr = x + (size_t)row*DD;
    float s = 0.f;
    #pragma unroll
    for (int i = 0; i < DD/256; i++){ float v = xr[tid + i*256]; s += v*v; }
    red[tid] = s; __syncthreads();
    for (int off = 128; off > 0; off >>= 1){ if (tid < off) red[tid] += red[tid+off]; __syncthreads(); }
    float nr = rsqrtf(red[0]/(float)DD + 1e-6f);
    float* orow = out + (size_t)row*DD;
    #pragma unroll
    for (int i = 0; i < DD/256; i++){ int c = tid + i*256; orow[c] = xr[c]*nr*w[c]; }
}

// ---------------- TF32 tensor-core GEMM 128x128x32, 8 warps -----------------
// EPI: 0 = bias only
//      1 = s2i: (acc+bias + ep2[col]*ep1[row*N+col]) * sigmoid(ep3[row*ep_stride+col])
//      2 = residual: acc+bias + ep1[row*ep_stride+col]
//      3 = gelu(acc+bias) (exact, erf)
//      4 = moe accumulate: C[row,col] += ep1[row*4] * (acc+bias)
#define AS_STRIDE 33
#define BS_STRIDE 129

template<int EPI>
__device__ __forceinline__ void epi_store(
    float* __restrict__ C, int row, int col, int N, float acc,
    const float* __restrict__ bias,
    const float* __restrict__ ep1, const float* __restrict__ ep2,
    const float* __restrict__ ep3, int ep_stride)
{
    float v = acc + bias[col];
    if (EPI == 1) {
        v += ep2[col]*ep1[(size_t)row*N + col];
        v *= sigmoidf_(ep3[(size_t)row*ep_stride + col]);
    } else if (EPI == 2) {
        v += ep1[(size_t)row*ep_stride + col];
    } else if (EPI == 3) {
        v = 0.5f*v*(1.f + erff(v*0.70710678118654752f));
    }
    if (EPI == 4) C[(size_t)row*N + col] += ep1[(size_t)row*4]*v;
    else          C[(size_t)row*N + col] = v;
}

template<int EPI>
__global__ void __launch_bounds__(256) gemm_tf32(
    const float* __restrict__ A, const float* __restrict__ B,
    float* __restrict__ C, int M, int N, int K,
    const float* __restrict__ bias,
    const float* __restrict__ ep1, const float* __restrict__ ep2,
    const float* __restrict__ ep3, int ep_stride)
{
    __shared__ unsigned As[128*AS_STRIDE];
    __shared__ unsigned Bs[32*BS_STRIDE];
    int tid = threadIdx.x, lane = tid & 31, warp = tid >> 5;
    int wm = (warp >> 2)*64, wn = (warp & 3)*32;   // warp tile 64x32
    int rowBase = blockIdx.y*128, colBase = blockIdx.x*128;

    float acc[4][4][4];
    #pragma unroll
    for (int i=0;i<4;i++)
        #pragma unroll
        for (int j=0;j<4;j++)
            #pragma unroll
            for (int r=0;r<4;r++) acc[i][j][r]=0.f;

    int ar = tid >> 3, ac = (tid & 7)*4;     // A tile fill: 32 rows/pass
    int br = tid >> 5, bc = (tid & 31)*4;    // B tile fill: 8 rows/pass

    for (int k0 = 0; k0 < K; k0 += 32) {
        #pragma unroll
        for (int i=0;i<4;i++){
            int r = ar + 32*i;
            float4 v = *reinterpret_cast<const float4*>(&A[(size_t)(rowBase+r)*K + k0 + ac]);
            As[r*AS_STRIDE + ac+0] = f2tf(v.x);
            As[r*AS_STRIDE + ac+1] = f2tf(v.y);
            As[r*AS_STRIDE + ac+2] = f2tf(v.z);
            As[r*AS_STRIDE + ac+3] = f2tf(v.w);
        }
        #pragma unroll
        for (int i=0;i<4;i++){
            int r = br + 8*i;
            float4 v = *reinterpret_cast<const float4*>(&B[(size_t)(k0+r)*N + colBase + bc]);
            Bs[r*BS_STRIDE + bc+0] = f2tf(v.x);
            Bs[r*BS_STRIDE + bc+1] = f2tf(v.y);
            Bs[r*BS_STRIDE + bc+2] = f2tf(v.z);
            Bs[r*BS_STRIDE + bc+3] = f2tf(v.w);
        }
        __syncthreads();

        #pragma unroll
        for (int kk = 0; kk < 32; kk += 8){
            unsigned a[4][4], b[4][2];
            #pragma unroll
            for (int i=0;i<4;i++){
                int r = wm + i*16 + (lane>>2);
                int c = kk + (lane&3);
                a[i][0] = As[r*AS_STRIDE + c];
                a[i][1] = As[(r+8)*AS_STRIDE + c];
                a[i][2] = As[r*AS_STRIDE + c + 4];
                a[i][3] = As[(r+8)*AS_STRIDE + c + 4];
            }
            #pragma unroll
            for (int j=0;j<4;j++){
                int c = wn + j*8 + (lane>>2);
                b[j][0] = Bs[(kk + (lane&3))*BS_STRIDE + c];
                b[j][1] = Bs[(kk + (lane&3) + 4)*BS_STRIDE + c];
            }
            #pragma unroll
            for (int i=0;i<4;i++)
                #pragma unroll
                for (int j=0;j<4;j++){
                    asm volatile(
                        "mma.sync.aligned.m16n8k8.row.col.f32.tf32.tf32.f32 "
                        "{%0,%1,%2,%3}, {%4,%5,%6,%7}, {%8,%9}, {%0,%1,%2,%3};"
                        : "+f"(acc[i][j][0]), "+f"(acc[i][j][1]),
                          "+f"(acc[i][j][2]), "+f"(acc[i][j][3])
                        : "r"(a[i][0]), "r"(a[i][1]), "r"(a[i][2]), "r"(a[i][3]),
                          "r"(b[j][0]), "r"(b[j][1]));
                }
        }
        __syncthreads();
    }

    #pragma unroll
    for (int i=0;i<4;i++){
        #pragma unroll
        for (int j=0;j<4;j++){
            int r0 = rowBase + wm + i*16 + (lane>>2);
            int c0 = colBase + wn + j*8 + 2*(lane&3);
            epi_store<EPI>(C, r0,   c0,   N, acc[i][j][0], bias, ep1, ep2, ep3, ep_stride);
            epi_store<EPI>(C, r0,   c0+1, N, acc[i][j][1], bias, ep1, ep2, ep3, ep_stride);
            epi_store<EPI>(C, r0+8, c0,   N, acc[i][j][2], bias, ep1, ep2, ep3, ep_stride);
            epi_store<EPI>(C, r0+8, c0+1, N, acc[i][j][3], bias, ep1, ep2, ep3, ep_stride);
        }
    }
}

// ---------------- causal depthwise conv (K=3) + bias + silu ----------------
__global__ void conv_silu_kernel(const float* __restrict__ xz,
                                 const float* __restrict__ cw,
                                 const float* __restrict__ cb,
                                 float* __restrict__ xm)
{
    int idx = blockIdx.x*blockDim.x + threadIdx.x;
    if (idx >= MM*INNER) return;
    int c  = idx & (INNER-1);
    int rt = idx >> 11;
    int t  = rt & (TT-1);
    const float* w = cw + c*3;
    float v = w[2]*xz[(size_t)rt*(2*INNER) + c];
    if (t >= 1) v += w[1]*xz[(size_t)(rt-1)*(2*INNER) + c];
    if (t >= 2) v += w[0]*xz[(size_t)(rt-2)*(2*INNER) + c];
    v += cb[c];
    xm[(size_t)rt*INNER + c] = v * sigmoidf_(v);
}

// ---------------- dt/B/C projections: [M,2048]@[2048,64] -------------------
__global__ void __launch_bounds__(256) proj_kernel(
    const float* __restrict__ X,
    const float* __restrict__ Wdt, const float* __restrict__ Wb, const float* __restrict__ Wc,
    const float* __restrict__ bdt, const float* __restrict__ bb, const float* __restrict__ bc,
    float* __restrict__ odt, float* __restrict__ oB, float* __restrict__ oC)
{
    const int Kp = INNER;
    int mat = blockIdx.y;
    const float* W    = (mat==0)? Wdt : (mat==1)? Wb : Wc;
    const float* bias = (mat==0)? bdt : (mat==1)? bb : bc;
    float* out        = (mat==0)? odt : (mat==1)? oB : oC;
    __shared__ float Xs[32][64];
    __shared__ float Ws[32][64];
    int tid = threadIdx.x;
    int tx = tid & 15, ty = tid >> 4;
    int rowBase = blockIdx.x * 64;
    float acc[4][4];
    #pragma unroll
    for (int i=0;i<4;i++)
        #pragma unroll
        for (int j=0;j<4;j++) acc[i][j]=0.f;

    for (int k0 = 0; k0 < Kp; k0 += 32) {
        #pragma unroll
        for (int h=0; h<2; h++){
            int r = (tid>>3) + h*32;
            int c = (tid&7)*4;
            float4 v = *reinterpret_cast<const float4*>(&X[(size_t)(rowBase+r)*Kp + k0 + c]);
            Xs[c+0][r]=v.x; Xs[c+1][r]=v.y; Xs[c+2][r]=v.z; Xs[c+3][r]=v.w;
        }
        #pragma unroll
        for (int h=0; h<2; h++){
            int r = (tid>>4) + h*16;
            int c = (tid&15)*4;
            *reinterpret_cast<float4*>(&Ws[r][c]) =
                *reinterpret_cast<const float4*>(&W[(size_t)(k0+r)*64 + c]);
        }
        __syncthreads();
        #pragma unroll
        for (int k=0;k<32;k++){
            float a[4], b[4];
            #pragma unroll
            for (int i=0;i<4;i++) a[i]=Xs[k][ty*4+i];
            #pragma unroll
            for (int j=0;j<4;j++) b[j]=Ws[k][tx*4+j];
            #pragma unroll
            for (int i=0;i<4;i++)
                #pragma unroll
                for (int j=0;j<4;j++) acc[i][j]=fmaf(a[i],b[j],acc[i][j]);
        }
        __syncthreads();
    }
    #pragma unroll
    for (int i=0;i<4;i++){
        int row = rowBase + ty*4 + i;
        #pragma unroll
        for (int j=0;j<4;j++){
            int col = tx*4 + j;
            float v = acc[i][j] + bias[col];
            if (mat == 0) v = sigmoidf_(v);
            out[(size_t)row*64 + col] = v;
        }
    }
}

// ---------------- selective-scan ----------------
__global__ void scan_kernel(const float* __restrict__ dt, const float* __restrict__ Bm,
                            const float* __restrict__ Cm, float* __restrict__ y)
{
    __shared__ float sA[256], sU[256];
    int bs = blockIdx.x;
    int b = bs >> 6, s = bs & 63;
    int tid = threadIdx.x;
    size_t base = (size_t)b*TT*DSTATE + s;
    float a_l[8], u_l[8], c_l[8];
    float A = 1.f, U = 0.f;
    #pragma unroll
    for (int i=0;i<8;i++){
        int t = tid*8 + i;
        size_t off = base + (size_t)t*DSTATE;
        float d  = dt[off];
        float bb = Bm[off];
        c_l[i] = Cm[off];
        float a = 1.f - d, u = d*bb;
        a_l[i]=a; u_l[i]=u;
        U = a*U + u;  A = a*A;
    }
    sA[tid]=A; sU[tid]=U; __syncthreads();
    for (int off=1; off<256; off<<=1){
        float pa=1.f, pu=0.f;
        if (tid >= off){ pa = sA[tid-off]; pu = sU[tid-off]; }
        __syncthreads();
        if (tid >= off){ U = A*pu + U; A = A*pa; }
        sA[tid]=A; sU[tid]=U; __syncthreads();
    }
    float state = (tid > 0) ? sU[tid-1] : 0.f;
    #pragma unroll
    for (int i=0;i<8;i++){
        state = a_l[i]*state + u_l[i];
        int t = tid*8 + i;
        y[base + (size_t)t*DSTATE] = c_l[i]*state;
    }
}

// ---------------- layernorm over dim 64 ----------------
__global__ void ln64_kernel(float* __restrict__ y)
{
    __shared__ float red[64];
    __shared__ float mu_s, var_s;
    int row = blockIdx.x, tid = threadIdx.x;
    float v = y[(size_t)row*64 + tid];
    red[tid] = v; __syncthreads();
    for (int off=32; off>0; off>>=1){ if (tid<off) red[tid]+=red[tid+off]; __syncthreads(); }
    if (tid==0) mu_s = red[0]/64.f;
    __syncthreads();
    float d = v - mu_s;
    red[tid] = d*d; __syncthreads();
    for (int off=32; off>0; off>>=1){ if (tid<off) red[tid]+=red[tid+off]; __syncthreads(); }
    if (tid==0) var_s = red[0]/64.f;
    __syncthreads();
    y[(size_t)row*64 + tid] = d * rsqrtf(var_s + 1e-5f);
}

// ---------------- gating ----------------
__global__ void gate_kernel(const float* __restrict__ h2, const float* __restrict__ gw,
                            const float* __restrict__ gb, float* __restrict__ wf)
{
    __shared__ float red[4][128];
    int row = blockIdx.x, tid = threadIdx.x;
    float p[4] = {0.f,0.f,0.f,0.f};
    const float* hr = h2 + (size_t)row*DD;
    for (int d = tid; d < DD; d += 128){
        float hv = hr[d];
        #pragma unroll
        for (int e=0;e<4;e++) p[e] = fmaf(hv, gw[d*4+e], p[e]);
    }
    #pragma unroll
    for (int e=0;e<4;e++) red[e][tid]=p[e];
    __syncthreads();
    for (int off=64; off>0; off>>=1){
        if (tid < off) {
            #pragma unroll
            for (int e=0;e<4;e++) red[e][tid]+=red[e][tid+off];
        }
        __syncthreads();
    }
    if (tid == 0){
        float l[4];
        #pragma unroll
        for (int e=0;e<4;e++) l[e] = red[e][0] + gb[e];
        int i0 = 0;
        #pragma unroll
        for (int e=1;e<4;e++) if (l[e] > l[i0]) i0 = e;
        int i1 = -1;
        #pragma unroll
        for (int e=0;e<4;e++) if (e != i0 && (i1 < 0 || l[e] > l[i1])) i1 = e;
        float ex = expf(l[i1] - l[i0]);
        float p0 = 1.f/(1.f+ex), p1 = ex/(1.f+ex);
        float w[4] = {0.f,0.f,0.f,0.f};
        w[i0]=p0; w[i1]=p1;
        #pragma unroll
        for (int e=0;e<4;e++) wf[(size_t)row*4+e]=w[e];
    }
}

// ---------------- copy x1 -> d_out ----------------
__global__ void copy4_kernel(const float* __restrict__ src, float* __restrict__ dst, int n4)
{
    int i = blockIdx.x*blockDim.x + threadIdx.x;
    if (i < n4) reinterpret_cast<float4*>(dst)[i] = reinterpret_cast<const float4*>(src)[i];
}

// ---------------- host launcher ----------------
static float* sym(const void* s){ void* p=nullptr; cudaGetSymbolAddress(&p, s); return (float*)p; }

extern "C" void kernel_launch(void* const* d_in, const int* in_sizes, int n_in,
                              void* d_out, int out_size)
{
    const float* x        = (const float*)d_in[0];
    const float* norm1_w  = (const float*)d_in[1];
    const float* norm2_w  = (const float*)d_in[2];
    const float* in_proj_w= (const float*)d_in[3];
    const float* in_proj_b= (const float*)d_in[4];
    const float* conv_w   = (const float*)d_in[5];
    const float* conv_b   = (const float*)d_in[6];
    const float* dt_w     = (const float*)d_in[7];
    const float* dt_b     = (const float*)d_in[8];
    const float* bp_w     = (const float*)d_in[9];
    const float* bp_b     = (const float*)d_in[10];
    const float* cp_w     = (const float*)d_in[11];
    const float* cp_b     = (const float*)d_in[12];
    const float* s2i_w    = (const float*)d_in[13];
    const float* s2i_b    = (const float*)d_in[14];
    const float* D_param  = (const float*)d_in[15];
    const float* out_w    = (const float*)d_in[16];
    const float* out_b    = (const float*)d_in[17];
    const float* gate_w   = (const float*)d_in[18];
    const float* gate_b   = (const float*)d_in[19];
    const float* e_w1     = (const float*)d_in[20];
    const float* e_b1     = (const float*)d_in[21];
    const float* e_w2     = (const float*)d_in[22];
    const float* e_b2     = (const float*)d_in[23];
    float* out = (float*)d_out;

    float* p_h   = sym(g_h);
    float* p_xz  = sym(g_xz);
    float* p_xm  = sym(g_xm);
    float* p_dt  = sym(g_dt);
    float* p_Bm  = sym(g_Bm);
    float* p_Cm  = sym(g_Cm);
    float* p_y   = sym(g_y);
    float* p_y2  = sym(g_y2);
    float* p_x1  = sym(g_x1);
    float* p_h2  = sym(g_h2);
    float* p_wf  = sym(g_wf);
    float* p_hid = sym(g_hid);

    // 1. rmsnorm(x, norm1_w) -> h
    rmsnorm_kernel<<<MM, 256>>>(x, norm1_w, p_h);

    // 2. xz = h @ in_proj_w + b   [4096, 4096] K=1024
    gemm_tf32<0><<<dim3(2*INNER/128, MM/128), 256>>>(p_h, in_proj_w, p_xz,
        MM, 2*INNER, DD, in_proj_b, nullptr, nullptr, nullptr, 0);

    // 3. causal depthwise conv + silu -> x_main
    conv_silu_kernel<<<(MM*INNER)/256, 256>>>(p_xz, conv_w, conv_b, p_xm);

    // 4. dt (sigmoid), Bm, Cm
    proj_kernel<<<dim3(MM/64, 3), 256>>>(p_xm, dt_w, bp_w, cp_w, dt_b, bp_b, cp_b,
                                         p_dt, p_Bm, p_Cm);

    // 5. selective scan -> y
    scan_kernel<<<BB*DSTATE, 256>>>(p_dt, p_Bm, p_Cm, p_y);

    // 6. layernorm over 64
    ln64_kernel<<<MM, 64>>>(p_y);

    // 7. y2 = (y @ s2i_w + b + D*x_main) * sigmoid(gate)  K=64
    gemm_tf32<1><<<dim3(INNER/128, MM/128), 256>>>(p_y, s2i_w, p_y2,
        MM, INNER, DSTATE, s2i_b, p_xm, D_param, p_xz + INNER, 2*INNER);

    // 8. x1 = x + (y2 @ out_w + b)  K=2048
    gemm_tf32<2><<<dim3(DD/128, MM/128), 256>>>(p_y2, out_w, p_x1,
        MM, DD, INNER, out_b, x, nullptr, nullptr, DD);

    // 9. rmsnorm(x1, norm2_w) -> h2
    rmsnorm_kernel<<<MM, 256>>>(p_x1, norm2_w, p_h2);

    // 10. gating -> wf
    gate_kernel<<<MM, 128>>>(p_h2, gate_w, gate_b, p_wf);

    // 11. out = x1
    copy4_kernel<<<(MM*DD/4 + 255)/256, 256>>>(p_x1, out, MM*DD/4);

    // 12. per-expert MoE
    for (int e = 0; e < EE; e++){
        gemm_tf32<3><<<dim3(HID/128, MM/128), 256>>>(p_h2, e_w1 + (size_t)e*DD*HID, p_hid,
            MM, HID, DD, e_b1 + (size_t)e*HID, nullptr, nullptr, nullptr, 0);
        gemm_tf32<4><<<dim3(DD/128, MM/128), 256>>>(p_hid, e_w2 + (size_t)e*HID*DD, out,
            MM, DD, HID, e_b2 + (size_t)e*DD, p_wf + e, nullptr, nullptr, 0);
    }
}

// round 3
// speedup vs baseline: 3.7411x; 2.4686x over previous
#include <cuda_runtime.h>
#include <math.h>

// ---------------- problem constants ----------------
#define BB 2
#define TT 2048
#define DD 1024
#define MM (BB*TT)          // 4096 token rows
#define INNER 2048
#define DSTATE 64
#define EE 4
#define HID 4096

// ---------------- scratch (device globals; no allocation allowed) ----------
__device__ float g_h   [MM*DD];
__device__ float g_xz  [MM*2*INNER];
__device__ float g_xm  [MM*INNER];
__device__ float g_P   [MM*256];       // packed dt|B|C projections (+pad)
__device__ float g_y   [MM*DSTATE];
__device__ float g_y2  [MM*INNER];
__device__ float g_x1  [MM*DD];
__device__ float g_h2  [MM*DD];
__device__ float g_wf  [MM*EE];
__device__ float g_hid [MM*HID];
__device__ float g_Wp  [INNER*256];    // packed dt/B/C weights
__device__ float g_bp  [256];          // packed bias
__device__ int   g_idx [EE*MM];
__device__ int   g_cnt [EE];

// ---------------- helpers ----------------
__device__ __forceinline__ float sigmoidf_(float x){ return 1.f/(1.f+expf(-x)); }
__device__ __forceinline__ unsigned f2tf(float x){
    unsigned r; asm("cvt.rna.tf32.f32 %0, %1;" : "=r"(r) : "f"(x)); return r;
}
__device__ __forceinline__ void cpa16(unsigned dst, const void* src){
    asm volatile("cp.async.cg.shared.global [%0], [%1], 16;" :: "r"(dst), "l"(src));
}

// ---------------- rmsnorm ----------------
__global__ void rmsnorm_kernel(const float* __restrict__ x, const float* __restrict__ w,
                               float* __restrict__ out)
{
    __shared__ float red[256];
    int row = blockIdx.x, tid = threadIdx.x;
    const float* xr = x + (size_t)row*DD;
    float s = 0.f;
    #pragma unroll
    for (int i = 0; i < DD/256; i++){ float v = xr[tid + i*256]; s += v*v; }
    red[tid] = s; __syncthreads();
    for (int off = 128; off > 0; off >>= 1){ if (tid < off) red[tid] += red[tid+off]; __syncthreads(); }
    float nr = rsqrtf(red[0]/(float)DD + 1e-6f);
    float* orow = out + (size_t)row*DD;
    #pragma unroll
    for (int i = 0; i < DD/256; i++){ int c = tid + i*256; orow[c] = xr[c]*nr*w[c]; }
}

// ================= TF32 GEMM, cp.async double-buffered, 128x128x32 =========
// EPI: 0 bias | 1 s2i-gate | 2 residual | 5 gathered-A gelu | 6 scatter-add
#define AS_T 36
#define BS_T 136
#define A_STAGE (128*AS_T)
#define B_STAGE (32*BS_T)
#define SMEM_BYTES ((2*A_STAGE + 2*B_STAGE)*4)

template<int EPI>
__device__ __forceinline__ void epi_store(
    float* __restrict__ C, int row, int col, int N, float acc,
    const float* __restrict__ bias,
    const float* __restrict__ ep1, const float* __restrict__ ep2,
    const float* __restrict__ ep3, int ep_stride,
    const int* __restrict__ idx, int cnt)
{
    if ((EPI==5 || EPI==6) && row >= cnt) return;
    float v = acc + bias[col];
    if (EPI == 1) {
        v += ep2[col]*ep1[(size_t)row*N + col];
        v *= sigmoidf_(ep3[(size_t)row*ep_stride + col]);
    } else if (EPI == 2) {
        v += ep1[(size_t)row*ep_stride + col];
    } else if (EPI == 5) {
        v = 0.5f*v*(1.f + erff(v*0.70710678118654752f));
    }
    if (EPI == 6) {
        int gr = idx[row];
        C[(size_t)gr*N + col] += ep1[(size_t)gr*4]*v;
    } else {
        C[(size_t)row*N + col] = v;
    }
}

template<int EPI>
__global__ void __launch_bounds__(256) gemm_tf32(
    const float* __restrict__ A, const float* __restrict__ B,
    float* __restrict__ C, int M, int N, int K,
    const float* __restrict__ bias,
    const float* __restrict__ ep1, const float* __restrict__ ep2,
    const float* __restrict__ ep3, int ep_stride,
    const int* __restrict__ idx, const int* __restrict__ cnt_ptr)
{
    extern __shared__ float smem[];
    int tid = threadIdx.x, lane = tid & 31, warp = tid >> 5;
    int wm = (warp >> 2)*64, wn = (warp & 3)*32;
    int rowBase = blockIdx.y*128, colBase = blockIdx.x*128;

    int cnt = M;
    if (EPI==5 || EPI==6){
        cnt = *cnt_ptr;
        if (rowBase >= cnt) return;
    }

    // A fill mapping: r = tid>>1 (one row per 2 threads), 4 chunks of 4 floats
    int ar = tid >> 1;
    int acol = (tid & 1)*16;
    int arow_l = rowBase + ar;
    if (EPI==5 || EPI==6) arow_l = min(arow_l, cnt-1);
    int arow = (EPI==5) ? idx[arow_l] : arow_l;
    const float* aSrc = A + (size_t)arow*K + acol;
    // B fill mapping: k = tid>>3, 4 chunks of 4 floats across 128 cols
    int bk = tid >> 3;
    int bcol = (tid & 7)*4;
    const float* bSrc = B + (size_t)bk*N + colBase + bcol;

    unsigned asBase = (unsigned)__cvta_generic_to_shared(smem);
    unsigned bsBase = asBase + 2*A_STAGE*4;

    float acc[4][4][4];
    #pragma unroll
    for (int i=0;i<4;i++)
        #pragma unroll
        for (int j=0;j<4;j++)
            #pragma unroll
            for (int r=0;r<4;r++) acc[i][j][r]=0.f;

    int nk = K/32;

    // prologue: stage 0
    {
        unsigned ad = asBase + (ar*AS_T + acol)*4;
        #pragma unroll
        for (int j=0;j<4;j++) cpa16(ad + j*16, aSrc + j*4);
        unsigned bd = bsBase + (bk*BS_T + bcol)*4;
        #pragma unroll
        for (int j=0;j<4;j++) cpa16(bd + j*128, bSrc + j*32);
        asm volatile("cp.async.commit_group;");
    }

    for (int kt = 0; kt < nk; kt++){
        int cur = kt & 1;
        if (kt+1 < nk){
            int nxt = 1 - cur;
            int k0 = (kt+1)*32;
            unsigned ad = asBase + (nxt*A_STAGE + ar*AS_T + acol)*4;
            const float* as = aSrc + k0;
            #pragma unroll
            for (int j=0;j<4;j++) cpa16(ad + j*16, as + j*4);
            unsigned bd = bsBase + (nxt*B_STAGE + bk*BS_T + bcol)*4;
            const float* bs = bSrc + (size_t)k0*N;
            #pragma unroll
            for (int j=0;j<4;j++) cpa16(bd + j*128, bs + j*32);
            asm volatile("cp.async.commit_group;");
            asm volatile("cp.async.wait_group 1;");
        } else {
            asm volatile("cp.async.wait_group 0;");
        }
        __syncthreads();

        const float* As = smem + cur*A_STAGE;
        const float* Bs = smem + 2*A_STAGE + cur*B_STAGE;

        #pragma unroll
        for (int kk = 0; kk < 32; kk += 8){
            unsigned a[4][4], b[4][2];
            int c = kk + (lane&3);
            #pragma unroll
            for (int i=0;i<4;i++){
                int r = wm + i*16 + (lane>>2);
                a[i][0] = f2tf(As[r*AS_T + c]);
                a[i][1] = f2tf(As[(r+8)*AS_T + c]);
                a[i][2] = f2tf(As[r*AS_T + c + 4]);
                a[i][3] = f2tf(As[(r+8)*AS_T + c + 4]);
            }
            #pragma unroll
            for (int j=0;j<4;j++){
                int cb = wn + j*8 + (lane>>2);
                b[j][0] = f2tf(Bs[c*BS_T + cb]);
                b[j][1] = f2tf(Bs[(c+4)*BS_T + cb]);
            }
            #pragma unroll
            for (int i=0;i<4;i++)
                #pragma unroll
                for (int j=0;j<4;j++){
                    asm volatile(
                        "mma.sync.aligned.m16n8k8.row.col.f32.tf32.tf32.f32 "
                        "{%0,%1,%2,%3}, {%4,%5,%6,%7}, {%8,%9}, {%0,%1,%2,%3};"
                        : "+f"(acc[i][j][0]), "+f"(acc[i][j][1]),
                          "+f"(acc[i][j][2]), "+f"(acc[i][j][3])
                        : "r"(a[i][0]), "r"(a[i][1]), "r"(a[i][2]), "r"(a[i][3]),
                          "r"(b[j][0]), "r"(b[j][1]));
                }
        }
        __syncthreads();
    }

    #pragma unroll
    for (int i=0;i<4;i++){
        #pragma unroll
        for (int j=0;j<4;j++){
            int r0 = rowBase + wm + i*16 + (lane>>2);
            int c0 = colBase + wn + j*8 + 2*(lane&3);
            epi_store<EPI>(C, r0,   c0,   N, acc[i][j][0], bias, ep1, ep2, ep3, ep_stride, idx, cnt);
            epi_store<EPI>(C, r0,   c0+1, N, acc[i][j][1], bias, ep1, ep2, ep3, ep_stride, idx, cnt);
            epi_store<EPI>(C, r0+8, c0,   N, acc[i][j][2], bias, ep1, ep2, ep3, ep_stride, idx, cnt);
            epi_store<EPI>(C, r0+8, c0+1, N, acc[i][j][3], bias, ep1, ep2, ep3, ep_stride, idx, cnt);
        }
    }
}

// ---------------- pack dt/B/C weights into [INNER, 256] + bias[256] --------
__global__ void pack_w_kernel(const float* __restrict__ dtw, const float* __restrict__ bpw,
                              const float* __restrict__ cpw, const float* __restrict__ dtb,
                              const float* __restrict__ bpb, const float* __restrict__ cpb,
                              float* __restrict__ W, float* __restrict__ bias)
{
    int i = blockIdx.x*blockDim.x + threadIdx.x;   // over INNER*256
    int k = i >> 8, c = i & 255;
    float v = 0.f;
    if      (c < 64)  v = dtw[k*64 + c];
    else if (c < 128) v = bpw[k*64 + c - 64];
    else if (c < 192) v = cpw[k*64 + c - 128];
    W[i] = v;
    if (i < 256){
        float b = 0.f;
        if      (i < 64)  b = dtb[i];
        else if (i < 128) b = bpb[i-64];
        else if (i < 192) b = cpb[i-128];
        bias[i] = b;
    }
}

// ---------------- causal depthwise conv (K=3) + bias + silu ----------------
__global__ void conv_silu_kernel(const float* __restrict__ xz,
                                 const float* __restrict__ cw,
                                 const float* __restrict__ cb,
                                 float* __restrict__ xm)
{
    int idx = blockIdx.x*blockDim.x + threadIdx.x;
    if (idx >= MM*INNER) return;
    int c  = idx & (INNER-1);
    int rt = idx >> 11;
    int t  = rt & (TT-1);
    const float* w = cw + c*3;
    float v = w[2]*xz[(size_t)rt*(2*INNER) + c];
    if (t >= 1) v += w[1]*xz[(size_t)(rt-1)*(2*INNER) + c];
    if (t >= 2) v += w[0]*xz[(size_t)(rt-2)*(2*INNER) + c];
    v += cb[c];
    xm[(size_t)rt*INNER + c] = v * sigmoidf_(v);
}

// ---------------- selective-scan over packed P [row,256] -------------------
__global__ void scan_kernel(const float* __restrict__ P, float* __restrict__ y)
{
    __shared__ float sA[256], sU[256];
    int bs = blockIdx.x;
    int b = bs >> 6, s = bs & 63;
    int tid = threadIdx.x;
    size_t baseP = (size_t)b*TT*256 + s;
    size_t baseY = (size_t)b*TT*DSTATE + s;
    float a_l[8], u_l[8], c_l[8];
    float A = 1.f, U = 0.f;
    #pragma unroll
    for (int i=0;i<8;i++){
        int t = tid*8 + i;
        size_t off = baseP + (size_t)t*256;
        float d  = sigmoidf_(P[off]);
        float bb = P[off + 64];
        c_l[i] = P[off + 128];
        float a = 1.f - d, u = d*bb;
        a_l[i]=a; u_l[i]=u;
        U = a*U + u;  A = a*A;
    }
    sA[tid]=A; sU[tid]=U; __syncthreads();
    for (int off=1; off<256; off<<=1){
        float pa=1.f, pu=0.f;
        if (tid >= off){ pa = sA[tid-off]; pu = sU[tid-off]; }
        __syncthreads();
        if (tid >= off){ U = A*pu + U; A = A*pa; }
        sA[tid]=A; sU[tid]=U; __syncthreads();
    }
    float state = (tid > 0) ? sU[tid-1] : 0.f;
    #pragma unroll
    for (int i=0;i<8;i++){
        state = a_l[i]*state + u_l[i];
        int t = tid*8 + i;
        y[baseY + (size_t)t*DSTATE] = c_l[i]*state;
    }
}

// ---------------- layernorm over dim 64 ----------------
__global__ void ln64_kernel(float* __restrict__ y)
{
    __shared__ float red[64];
    __shared__ float mu_s, var_s;
    int row = blockIdx.x, tid = threadIdx.x;
    float v = y[(size_t)row*64 + tid];
    red[tid] = v; __syncthreads();
    for (int off=32; off>0; off>>=1){ if (tid<off) red[tid]+=red[tid+off]; __syncthreads(); }
    if (tid==0) mu_s = red[0]/64.f;
    __syncthreads();
    float d = v - mu_s;
    red[tid] = d*d; __syncthreads();
    for (int off=32; off>0; off>>=1){ if (tid<off) red[tid]+=red[tid+off]; __syncthreads(); }
    if (tid==0) var_s = red[0]/64.f;
    __syncthreads();
    y[(size_t)row*64 + tid] = d * rsqrtf(var_s + 1e-5f);
}

// ---------------- gating ----------------
__global__ void gate_kernel(const float* __restrict__ h2, const float* __restrict__ gw,
                            const float* __restrict__ gb, float* __restrict__ wf)
{
    __shared__ float red[4][128];
    int row = blockIdx.x, tid = threadIdx.x;
    float p[4] = {0.f,0.f,0.f,0.f};
    const float* hr = h2 + (size_t)row*DD;
    for (int d = tid; d < DD; d += 128){
        float hv = hr[d];
        #pragma unroll
        for (int e=0;e<4;e++) p[e] = fmaf(hv, gw[d*4+e], p[e]);
    }
    #pragma unroll
    for (int e=0;e<4;e++) red[e][tid]=p[e];
    __syncthreads();
    for (int off=64; off>0; off>>=1){
        if (tid < off) {
            #pragma unroll
            for (int e=0;e<4;e++) red[e][tid]+=red[e][tid+off];
        }
        __syncthreads();
    }
    if (tid == 0){
        float l[4];
        #pragma unroll
        for (int e=0;e<4;e++) l[e] = red[e][0] + gb[e];
        int i0 = 0;
        #pragma unroll
        for (int e=1;e<4;e++) if (l[e] > l[i0]) i0 = e;
        int i1 = -1;
        #pragma unroll
        for (int e=0;e<4;e++) if (e != i0 && (i1 < 0 || l[e] > l[i1])) i1 = e;
        float ex = expf(l[i1] - l[i0]);
        float p0 = 1.f/(1.f+ex), p1 = ex/(1.f+ex);
        float w[4] = {0.f,0.f,0.f,0.f};
        w[i0]=p0; w[i1]=p1;
        #pragma unroll
        for (int e=0;e<4;e++) wf[(size_t)row*4+e]=w[e];
    }
}

// ---------------- deterministic per-expert row compaction ------------------
__global__ void compact_kernel(const float* __restrict__ wf, int* __restrict__ idxs,
                               int* __restrict__ cnts)
{
    __shared__ int sbuf[256];
    int e = blockIdx.x, tid = threadIdx.x;
    int base = 0;
    for (int chunk = 0; chunk < MM/256; chunk++){
        int row = chunk*256 + tid;
        int p = (wf[(size_t)row*4 + e] > 0.f) ? 1 : 0;
        sbuf[tid] = p; __syncthreads();
        for (int off=1; off<256; off<<=1){
            int v = (tid >= off) ? sbuf[tid-off] : 0;
            __syncthreads();
            sbuf[tid] += v;
            __syncthreads();
        }
        if (p) idxs[(size_t)e*MM + base + sbuf[tid] - 1] = row;
        base += sbuf[255];
        __syncthreads();
    }
    if (tid == 0) cnts[e] = base;
}

// ---------------- copy x1 -> d_out ----------------
__global__ void copy4_kernel(const float* __restrict__ src, float* __restrict__ dst, int n4)
{
    int i = blockIdx.x*blockDim.x + threadIdx.x;
    if (i < n4) reinterpret_cast<float4*>(dst)[i] = reinterpret_cast<const float4*>(src)[i];
}

// ---------------- host launcher ----------------
static float* sym(const void* s){ void* p=nullptr; cudaGetSymbolAddress(&p, s); return (float*)p; }
static int*   symi(const void* s){ void* p=nullptr; cudaGetSymbolAddress(&p, s); return (int*)p; }

extern "C" void kernel_launch(void* const* d_in, const int* in_sizes, int n_in,
                              void* d_out, int out_size)
{
    const float* x        = (const float*)d_in[0];
    const float* norm1_w  = (const float*)d_in[1];
    const float* norm2_w  = (const float*)d_in[2];
    const float* in_proj_w= (const float*)d_in[3];
    const float* in_proj_b= (const float*)d_in[4];
    const float* conv_w   = (const float*)d_in[5];
    const float* conv_b   = (const float*)d_in[6];
    const float* dt_w     = (const float*)d_in[7];
    const float* dt_b     = (const float*)d_in[8];
    const float* bp_w     = (const float*)d_in[9];
    const float* bp_b     = (const float*)d_in[10];
    const float* cp_w     = (const float*)d_in[11];
    const float* cp_b     = (const float*)d_in[12];
    const float* s2i_w    = (const float*)d_in[13];
    const float* s2i_b    = (const float*)d_in[14];
    const float* D_param  = (const float*)d_in[15];
    const float* out_w    = (const float*)d_in[16];
    const float* out_b    = (const float*)d_in[17];
    const float* gate_w   = (const float*)d_in[18];
    const float* gate_b   = (const float*)d_in[19];
    const float* e_w1     = (const float*)d_in[20];
    const float* e_b1     = (const float*)d_in[21];
    const float* e_w2     = (const float*)d_in[22];
    const float* e_b2     = (const float*)d_in[23];
    float* out = (float*)d_out;

    float* p_h   = sym(g_h);
    float* p_xz  = sym(g_xz);
    float* p_xm  = sym(g_xm);
    float* p_P   = sym(g_P);
    float* p_y   = sym(g_y);
    float* p_y2  = sym(g_y2);
    float* p_x1  = sym(g_x1);
    float* p_h2  = sym(g_h2);
    float* p_wf  = sym(g_wf);
    float* p_hid = sym(g_hid);
    float* p_Wp  = sym(g_Wp);
    float* p_bp  = sym(g_bp);
    int*   p_idx = symi(g_idx);
    int*   p_cnt = symi(g_cnt);

    cudaFuncSetAttribute(gemm_tf32<0>, cudaFuncAttributeMaxDynamicSharedMemorySize, SMEM_BYTES);
    cudaFuncSetAttribute(gemm_tf32<1>, cudaFuncAttributeMaxDynamicSharedMemorySize, SMEM_BYTES);
    cudaFuncSetAttribute(gemm_tf32<2>, cudaFuncAttributeMaxDynamicSharedMemorySize, SMEM_BYTES);
    cudaFuncSetAttribute(gemm_tf32<5>, cudaFuncAttributeMaxDynamicSharedMemorySize, SMEM_BYTES);
    cudaFuncSetAttribute(gemm_tf32<6>, cudaFuncAttributeMaxDynamicSharedMemorySize, SMEM_BYTES);

    // 0. pack dt/B/C weights
    pack_w_kernel<<<(INNER*256)/256, 256>>>(dt_w, bp_w, cp_w, dt_b, bp_b, cp_b, p_Wp, p_bp);

    // 1. rmsnorm(x) -> h
    rmsnorm_kernel<<<MM, 256>>>(x, norm1_w, p_h);

    // 2. xz = h @ in_proj_w + b  [4096,4096] K=1024
    gemm_tf32<0><<<dim3(2*INNER/128, MM/128), 256, SMEM_BYTES>>>(p_h, in_proj_w, p_xz,
        MM, 2*INNER, DD, in_proj_b, nullptr, nullptr, nullptr, 0, nullptr, nullptr);

    // 3. conv + silu -> x_main
    conv_silu_kernel<<<(MM*INNER)/256, 256>>>(p_xz, conv_w, conv_b, p_xm);

    // 4. P = xm @ Wp + bp  [4096,256] K=2048 (dt|B|C packed)
    gemm_tf32<0><<<dim3(256/128, MM/128), 256, SMEM_BYTES>>>(p_xm, p_Wp, p_P,
        MM, 256, INNER, p_bp, nullptr, nullptr, nullptr, 0, nullptr, nullptr);

    // 5. selective scan (applies sigmoid to dt) -> y
    scan_kernel<<<BB*DSTATE, 256>>>(p_P, p_y);

    // 6. layernorm over 64
    ln64_kernel<<<MM, 64>>>(p_y);

    // 7. y2 = (y @ s2i_w + b + D*x_main) * sigmoid(gate)  K=64
    gemm_tf32<1><<<dim3(INNER/128, MM/128), 256, SMEM_BYTES>>>(p_y, s2i_w, p_y2,
        MM, INNER, DSTATE, s2i_b, p_xm, D_param, p_xz + INNER, 2*INNER, nullptr, nullptr);

    // 8. x1 = x + (y2 @ out_w + b)  K=2048
    gemm_tf32<2><<<dim3(DD/128, MM/128), 256, SMEM_BYTES>>>(p_y2, out_w, p_x1,
        MM, DD, INNER, out_b, x, nullptr, nullptr, DD, nullptr, nullptr);

    // 9. rmsnorm(x1) -> h2
    rmsnorm_kernel<<<MM, 256>>>(p_x1, norm2_w, p_h2);

    // 10. gating -> wf ; compaction -> idx/cnt
    gate_kernel<<<MM, 128>>>(p_h2, gate_w, gate_b, p_wf);
    compact_kernel<<<EE, 256>>>(p_wf, p_idx, p_cnt);

    // 11. out = x1
    copy4_kernel<<<(MM*DD/4 + 255)/256, 256>>>(p_x1, out, MM*DD/4);

    // 12. per-expert compacted MoE
    for (int e = 0; e < EE; e++){
        // hid[r] = gelu(h2[idx[r]] @ w1 + b1)
        gemm_tf32<5><<<dim3(HID/128, MM/128), 256, SMEM_BYTES>>>(p_h2, e_w1 + (size_t)e*DD*HID, p_hid,
            MM, HID, DD, e_b1 + (size_t)e*HID, nullptr, nullptr, nullptr, 0,
            p_idx + (size_t)e*MM, p_cnt + e);
        // out[idx[r]] += wf[idx[r],e] * (hid[r] @ w2 + b2)
        gemm_tf32<6><<<dim3(DD/128, MM/128), 256, SMEM_BYTES>>>(p_hid, e_w2 + (size_t)e*HID*DD, out,
            MM, DD, HID, e_b2 + (size_t)e*DD, p_wf + e, nullptr, nullptr, 0,
            p_idx + (size_t)e*MM, p_cnt + e);
    }
}

// round 7
// speedup vs baseline: 3.8499x; 1.0291x over previous
#include <cuda_runtime.h>
#include <math.h>

// ---------------- problem constants ----------------
#define BB 2
#define TT 2048
#define DD 1024
#define MM (BB*TT)          // 4096 token rows
#define INNER 2048
#define DSTATE 64
#define EE 4
#define HID 4096

// ---------------- scratch (device globals; no allocation allowed) ----------
__device__ float g_h   [MM*DD];        // rmsnorm1 output (tf32-rounded)
__device__ float g_xz  [MM*2*INNER];   // exact
__device__ float g_xm  [MM*INNER];     // exact (epilogue use)
__device__ float g_xmr [MM*INNER];     // tf32-rounded (GEMM A)
__device__ float g_P   [MM*256];       // packed dt|B|C projections (exact)
__device__ float g_y   [MM*DSTATE];    // ln64 output (tf32-rounded)
__device__ float g_y2  [MM*INNER];     // tf32-rounded
__device__ float g_x1  [MM*DD];        // exact
__device__ float g_h2  [MM*DD];        // exact (gating)
__device__ float g_h2r [MM*DD];        // tf32-rounded (GEMM A)
__device__ float g_wf  [MM*EE];
__device__ float g_hid [MM*HID];       // tf32-rounded
__device__ float g_Wp  [INNER*256];    // packed dt/B/C weights (rounded)
__device__ float g_bp  [256];
__device__ int   g_idx [EE*MM];
__device__ int   g_cnt [EE];
// rounded weight copies
__device__ float g_w_in [DD*2*INNER];
__device__ float g_w_s2i[DSTATE*INNER];
__device__ float g_w_out[INNER*DD];
__device__ float g_w_e1 [EE*DD*HID];
__device__ float g_w_e2 [EE*HID*DD];

// ---------------- helpers ----------------
__device__ __forceinline__ float sigmoidf_(float x){ return 1.f/(1.f+expf(-x)); }
__device__ __forceinline__ float rndf(float x){
    unsigned r; asm("cvt.rna.tf32.f32 %0, %1;" : "=r"(r) : "f"(x));
    return __uint_as_float(r);
}
__device__ __forceinline__ void cpa16(unsigned dst, const void* src){
    asm volatile("cp.async.cg.shared.global [%0], [%1], 16;" :: "r"(dst), "l"(src));
}

// ---------------- weight rounding pass (float4) ----------------
__global__ void round_kernel(const float* __restrict__ src, float* __restrict__ dst, int n4)
{
    int i = blockIdx.x*blockDim.x + threadIdx.x;
    if (i >= n4) return;
    float4 v = reinterpret_cast<const float4*>(src)[i];
    v.x = rndf(v.x); v.y = rndf(v.y); v.z = rndf(v.z); v.w = rndf(v.w);
    reinterpret_cast<float4*>(dst)[i] = v;
}

// ---------------- rmsnorm: rounded primary output, optional exact copy -----
__global__ void rmsnorm_kernel(const float* __restrict__ x, const float* __restrict__ w,
                               float* __restrict__ out_r, float* __restrict__ out_exact)
{
    __shared__ float red[256];
    int row = blockIdx.x, tid = threadIdx.x;
    const float* xr = x + (size_t)row*DD;
    float s = 0.f;
    #pragma unroll
    for (int i = 0; i < DD/256; i++){ float v = xr[tid + i*256]; s += v*v; }
    red[tid] = s; __syncthreads();
    for (int off = 128; off > 0; off >>= 1){ if (tid < off) red[tid] += red[tid+off]; __syncthreads(); }
    float nr = rsqrtf(red[0]/(float)DD + 1e-6f);
    #pragma unroll
    for (int i = 0; i < DD/256; i++){
        int c = tid + i*256;
        float v = xr[c]*nr*w[c];
        out_r[(size_t)row*DD + c] = rndf(v);
        if (out_exact) out_exact[(size_t)row*DD + c] = v;
    }
}

// ================= TF32 GEMM, cp.async 3-stage, 128x128x32 ==================
// All A/B inputs pre-rounded to tf32 -> raw bit feed, no cvt in hot loop.
// EPI: 0 bias | 1 s2i-gate (rounded store) | 2 residual+dual-store (exact)
//      5 gathered-A gelu (rounded store) | 6 scatter-add (exact accumulate)
#define AS_T 36
#define BS_T 136
#define A_STAGE (128*AS_T)
#define B_STAGE (32*BS_T)
#define NSTAGE 3
#define SMEM_BYTES ((NSTAGE*A_STAGE + NSTAGE*B_STAGE)*4)

template<int EPI>
__device__ __forceinline__ void epi_store(
    float* __restrict__ C, int row, int col, int N, float acc,
    const float* __restrict__ bias,
    const float* __restrict__ ep1, const float* __restrict__ ep2,
    const float* __restrict__ ep3, int ep_stride,
    const int* __restrict__ idx, int cnt)
{
    if ((EPI==5 || EPI==6) && row >= cnt) return;
    float v = acc + bias[col];
    if (EPI == 1) {
        v += ep2[col]*ep1[(size_t)row*N + col];
        v *= sigmoidf_(ep3[(size_t)row*ep_stride + col]);
        v = rndf(v);                                   // next GEMM A input
    } else if (EPI == 2) {
        v += ep1[(size_t)row*ep_stride + col];
    } else if (EPI == 5) {
        v = 0.5f*v*(1.f + erff(v*0.70710678118654752f));
        v = rndf(v);                                   // next GEMM A input
    }
    if (EPI == 6) {
        int gr = idx[row];
        C[(size_t)gr*N + col] += ep1[(size_t)gr*4]*v;
    } else {
        C[(size_t)row*N + col] = v;
        if (EPI == 2) ((float*)ep2)[(size_t)row*N + col] = v;   // dual store -> d_out
    }
}

template<int EPI>
__global__ void __launch_bounds__(256) gemm_tf32(
    const float* __restrict__ A, const float* __restrict__ B,
    float* __restrict__ C, int M, int N, int K,
    const float* __restrict__ bias,
    const float* __restrict__ ep1, const float* __restrict__ ep2,
    const float* __restrict__ ep3, int ep_stride,
    const int* __restrict__ idx, const int* __restrict__ cnt_ptr)
{
    extern __shared__ float smem[];
    int tid = threadIdx.x, lane = tid & 31, warp = tid >> 5;
    int wm = (warp >> 2)*64, wn = (warp & 3)*32;
    int rowBase = blockIdx.y*128, colBase = blockIdx.x*128;

    int cnt = M;
    if (EPI==5 || EPI==6){
        cnt = *cnt_ptr;
        if (rowBase >= cnt) return;
    }

    int ar = tid >> 1;
    int acol = (tid & 1)*16;
    int arow_l = rowBase + ar;
    if (EPI==5 || EPI==6) arow_l = min(arow_l, cnt-1);
    int arow = (EPI==5) ? idx[arow_l] : arow_l;
    const float* aSrc = A + (size_t)arow*K + acol;
    int bk = tid >> 3;
    int bcol = (tid & 7)*4;
    const float* bSrc = B + (size_t)bk*N + colBase + bcol;

    unsigned asBase = (unsigned)__cvta_generic_to_shared(smem);
    unsigned bsBase = asBase + NSTAGE*A_STAGE*4;

    float acc[4][4][4];
    #pragma unroll
    for (int i=0;i<4;i++)
        #pragma unroll
        for (int j=0;j<4;j++)
            #pragma unroll
            for (int r=0;r<4;r++) acc[i][j][r]=0.f;

    int nk = K/32;

    // prologue: stages 0,1
    #pragma unroll
    for (int s = 0; s < 2; s++){
        if (s < nk){
            int k0 = s*32;
            unsigned ad = asBase + (s*A_STAGE + ar*AS_T + acol)*4;
            const float* as = aSrc + k0;
            #pragma unroll
            for (int j=0;j<4;j++) cpa16(ad + j*16, as + j*4);
            unsigned bd = bsBase + (s*B_STAGE + bk*BS_T + bcol)*4;
            const float* bs = bSrc + (size_t)k0*N;
            #pragma unroll
            for (int j=0;j<4;j++) cpa16(bd + j*128, bs + j*32);
            asm volatile("cp.async.commit_group;");
        }
    }

    for (int kt = 0; kt < nk; kt++){
        if (kt+2 < nk){
            int stg = (kt+2)%NSTAGE;
            int k0 = (kt+2)*32;
            unsigned ad = asBase + (stg*A_STAGE + ar*AS_T + acol)*4;
            const float* as = aSrc + k0;
            #pragma unroll
            for (int j=0;j<4;j++) cpa16(ad + j*16, as + j*4);
            unsigned bd = bsBase + (stg*B_STAGE + bk*BS_T + bcol)*4;
            const float* bs = bSrc + (size_t)k0*N;
            #pragma unroll
            for (int j=0;j<4;j++) cpa16(bd + j*128, bs + j*32);
            asm volatile("cp.async.commit_group;");
            asm volatile("cp.async.wait_group 2;");
        } else if (kt+1 < nk){
            asm volatile("cp.async.wait_group 1;");
        } else {
            asm volatile("cp.async.wait_group 0;");
        }
        __syncthreads();

        int cur = kt % NSTAGE;
        const float* As = smem + cur*A_STAGE;
        const float* Bs = smem + NSTAGE*A_STAGE + cur*B_STAGE;

        #pragma unroll
        for (int kk = 0; kk < 32; kk += 8){
            unsigned a[4][4], b[4][2];
            int c = kk + (lane&3);
            #pragma unroll
            for (int i=0;i<4;i++){
                int r = wm + i*16 + (lane>>2);
                a[i][0] = __float_as_uint(As[r*AS_T + c]);
                a[i][1] = __float_as_uint(As[(r+8)*AS_T + c]);
                a[i][2] = __float_as_uint(As[r*AS_T + c + 4]);
                a[i][3] = __float_as_uint(As[(r+8)*AS_T + c + 4]);
            }
            #pragma unroll
            for (int j=0;j<4;j++){
                int cb = wn + j*8 + (lane>>2);
                b[j][0] = __float_as_uint(Bs[c*BS_T + cb]);
                b[j][1] = __float_as_uint(Bs[(c+4)*BS_T + cb]);
            }
            #pragma unroll
            for (int i=0;i<4;i++)
                #pragma unroll
                for (int j=0;j<4;j++){
                    asm volatile(
                        "mma.sync.aligned.m16n8k8.row.col.f32.tf32.tf32.f32 "
                        "{%0,%1,%2,%3}, {%4,%5,%6,%7}, {%8,%9}, {%0,%1,%2,%3};"
                        : "+f"(acc[i][j][0]), "+f"(acc[i][j][1]),
                          "+f"(acc[i][j][2]), "+f"(acc[i][j][3])
                        : "r"(a[i][0]), "r"(a[i][1]), "r"(a[i][2]), "r"(a[i][3]),
                          "r"(b[j][0]), "r"(b[j][1]));
                }
        }
        __syncthreads();
    }

    #pragma unroll
    for (int i=0;i<4;i++){
        #pragma unroll
        for (int j=0;j<4;j++){
            int r0 = rowBase + wm + i*16 + (lane>>2);
            int c0 = colBase + wn + j*8 + 2*(lane&3);
            epi_store<EPI>(C, r0,   c0,   N, acc[i][j][0], bias, ep1, ep2, ep3, ep_stride, idx, cnt);
            epi_store<EPI>(C, r0,   c0+1, N, acc[i][j][1], bias, ep1, ep2, ep3, ep_stride, idx, cnt);
            epi_store<EPI>(C, r0+8, c0,   N, acc[i][j][2], bias, ep1, ep2, ep3, ep_stride, idx, cnt);
            epi_store<EPI>(C, r0+8, c0+1, N, acc[i][j][3], bias, ep1, ep2, ep3, ep_stride, idx, cnt);
        }
    }
}

// ---------------- pack dt/B/C weights into [INNER, 256] (rounded) ----------
__global__ void pack_w_kernel(const float* __restrict__ dtw, const float* __restrict__ bpw,
                              const float* __restrict__ cpw, const float* __restrict__ dtb,
                              const float* __restrict__ bpb, const float* __restrict__ cpb,
                              float* __restrict__ W, float* __restrict__ bias)
{
    int i = blockIdx.x*blockDim.x + threadIdx.x;
    int k = i >> 8, c = i & 255;
    float v = 0.f;
    if      (c < 64)  v = dtw[k*64 + c];
    else if (c < 128) v = bpw[k*64 + c - 64];
    else if (c < 192) v = cpw[k*64 + c - 128];
    W[i] = rndf(v);
    if (i < 256){
        float b = 0.f;
        if      (i < 64)  b = dtb[i];
        else if (i < 128) b = bpb[i-64];
        else if (i < 192) b = cpb[i-128];
        bias[i] = b;
    }
}

// ---------------- causal depthwise conv (K=3) + bias + silu ----------------
__global__ void conv_silu_kernel(const float* __restrict__ xz,
                                 const float* __restrict__ cw,
                                 const float* __restrict__ cb,
                                 float* __restrict__ xm, float* __restrict__ xmr)
{
    int idx = blockIdx.x*blockDim.x + threadIdx.x;
    if (idx >= MM*INNER) return;
    int c  = idx & (INNER-1);
    int rt = idx >> 11;
    int t  = rt & (TT-1);
    const float* w = cw + c*3;
    float v = w[2]*xz[(size_t)rt*(2*INNER) + c];
    if (t >= 1) v += w[1]*xz[(size_t)(rt-1)*(2*INNER) + c];
    if (t >= 2) v += w[0]*xz[(size_t)(rt-2)*(2*INNER) + c];
    v += cb[c];
    float s = v * sigmoidf_(v);
    xm [(size_t)rt*INNER + c] = s;
    xmr[(size_t)rt*INNER + c] = rndf(s);
}

// ---------------- selective-scan over packed P [row,256] -------------------
__global__ void scan_kernel(const float* __restrict__ P, float* __restrict__ y)
{
    __shared__ float sA[256], sU[256];
    int bs = blockIdx.x;
    int b = bs >> 6, s = bs & 63;
    int tid = threadIdx.x;
    size_t baseP = (size_t)b*TT*256 + s;
    size_t baseY = (size_t)b*TT*DSTATE + s;
    float a_l[8], u_l[8], c_l[8];
    float A = 1.f, U = 0.f;
    #pragma unroll
    for (int i=0;i<8;i++){
        int t = tid*8 + i;
        size_t off = baseP + (size_t)t*256;
        float d  = sigmoidf_(P[off]);
        float bb = P[off + 64];
        c_l[i] = P[off + 128];
        float a = 1.f - d, u = d*bb;
        a_l[i]=a; u_l[i]=u;
        U = a*U + u;  A = a*A;
    }
    sA[tid]=A; sU[tid]=U; __syncthreads();
    for (int off=1; off<256; off<<=1){
        float pa=1.f, pu=0.f;
        if (tid >= off){ pa = sA[tid-off]; pu = sU[tid-off]; }
        __syncthreads();
        if (tid >= off){ U = A*pu + U; A = A*pa; }
        sA[tid]=A; sU[tid]=U; __syncthreads();
    }
    float state = (tid > 0) ? sU[tid-1] : 0.f;
    #pragma unroll
    for (int i=0;i<8;i++){
        state = a_l[i]*state + u_l[i];
        int t = tid*8 + i;
        y[baseY + (size_t)t*DSTATE] = c_l[i]*state;
    }
}

// ---------------- layernorm over dim 64 (rounded output) -------------------
__global__ void ln64_kernel(float* __restrict__ y)
{
    __shared__ float red[64];
    __shared__ float mu_s, var_s;
    int row = blockIdx.x, tid = threadIdx.x;
    float v = y[(size_t)row*64 + tid];
    red[tid] = v; __syncthreads();
    for (int off=32; off>0; off>>=1){ if (tid<off) red[tid]+=red[tid+off]; __syncthreads(); }
    if (tid==0) mu_s = red[0]/64.f;
    __syncthreads();
    float d = v - mu_s;
    red[tid] = d*d; __syncthreads();
    for (int off=32; off>0; off>>=1){ if (tid<off) red[tid]+=red[tid+off]; __syncthreads(); }
    if (tid==0) var_s = red[0]/64.f;
    __syncthreads();
    y[(size_t)row*64 + tid] = rndf(d * rsqrtf(var_s + 1e-5f));
}

// ---------------- gating ----------------
__global__ void gate_kernel(const float* __restrict__ h2, const float* __restrict__ gw,
                            const float* __restrict__ gb, float* __restrict__ wf)
{
    __shared__ float red[4][128];
    int row = blockIdx.x, tid = threadIdx.x;
    float p[4] = {0.f,0.f,0.f,0.f};
    const float* hr = h2 + (size_t)row*DD;
    for (int d = tid; d < DD; d += 128){
        float hv = hr[d];
        #pragma unroll
        for (int e=0;e<4;e++) p[e] = fmaf(hv, gw[d*4+e], p[e]);
    }
    #pragma unroll
    for (int e=0;e<4;e++) red[e][tid]=p[e];
    __syncthreads();
    for (int off=64; off>0; off>>=1){
        if (tid < off) {
            #pragma unroll
            for (int e=0;e<4;e++) red[e][tid]+=red[e][tid+off];
        }
        __syncthreads();
    }
    if (tid == 0){
        float l[4];
        #pragma unroll
        for (int e=0;e<4;e++) l[e] = red[e][0] + gb[e];
        int i0 = 0;
        #pragma unroll
        for (int e=1;e<4;e++) if (l[e] > l[i0]) i0 = e;
        int i1 = -1;
        #pragma unroll
        for (int e=0;e<4;e++) if (e != i0 && (i1 < 0 || l[e] > l[i1])) i1 = e;
        float ex = expf(l[i1] - l[i0]);
        float p0 = 1.f/(1.f+ex), p1 = ex/(1.f+ex);
        float w[4] = {0.f,0.f,0.f,0.f};
        w[i0]=p0; w[i1]=p1;
        #pragma unroll
        for (int e=0;e<4;e++) wf[(size_t)row*4+e]=w[e];
    }
}

// ---------------- deterministic per-expert row compaction ------------------
__global__ void compact_kernel(const float* __restrict__ wf, int* __restrict__ idxs,
                               int* __restrict__ cnts)
{
    __shared__ int sbuf[256];
    int e = blockIdx.x, tid = threadIdx.x;
    int base = 0;
    for (int chunk = 0; chunk < MM/256; chunk++){
        int row = chunk*256 + tid;
        int p = (wf[(size_t)row*4 + e] > 0.f) ? 1 : 0;
        sbuf[tid] = p; __syncthreads();
        for (int off=1; off<256; off<<=1){
            int v = (tid >= off) ? sbuf[tid-off] : 0;
            __syncthreads();
            sbuf[tid] += v;
            __syncthreads();
        }
        if (p) idxs[(size_t)e*MM + base + sbuf[tid] - 1] = row;
        base += sbuf[255];
        __syncthreads();
    }
    if (tid == 0) cnts[e] = base;
}

// ---------------- host launcher ----------------
static float* sym(const void* s){ void* p=nullptr; cudaGetSymbolAddress(&p, s); return (float*)p; }
static int*   symi(const void* s){ void* p=nullptr; cudaGetSymbolAddress(&p, s); return (int*)p; }

extern "C" void kernel_launch(void* const* d_in, const int* in_sizes, int n_in,
                              void* d_out, int out_size)
{
    const float* x        = (const float*)d_in[0];
    const float* norm1_w  = (const float*)d_in[1];
    const float* norm2_w  = (const float*)d_in[2];
    const float* in_proj_w= (const float*)d_in[3];
    const float* in_proj_b= (const float*)d_in[4];
    const float* conv_w   = (const float*)d_in[5];
    const float* conv_b   = (const float*)d_in[6];
    const float* dt_w     = (const float*)d_in[7];
    const float* dt_b     = (const float*)d_in[8];
    const float* bp_w     = (const float*)d_in[9];
    const float* bp_b     = (const float*)d_in[10];
    const float* cp_w     = (const float*)d_in[11];
    const float* cp_b     = (const float*)d_in[12];
    const float* s2i_w    = (const float*)d_in[13];
    const float* s2i_b    = (const float*)d_in[14];
    const float* D_param  = (const float*)d_in[15];
    const float* out_w    = (const float*)d_in[16];
    const float* out_b    = (const float*)d_in[17];
    const float* gate_w   = (const float*)d_in[18];
    const float* gate_b   = (const float*)d_in[19];
    const float* e_w1     = (const float*)d_in[20];
    const float* e_b1     = (const float*)d_in[21];
    const float* e_w2     = (const float*)d_in[22];
    const float* e_b2     = (const float*)d_in[23];
    float* out = (float*)d_out;

    float* p_h    = sym(g_h);
    float* p_xz   = sym(g_xz);
    float* p_xm   = sym(g_xm);
    float* p_xmr  = sym(g_xmr);
    float* p_P    = sym(g_P);
    float* p_y    = sym(g_y);
    float* p_y2   = sym(g_y2);
    float* p_x1   = sym(g_x1);
    float* p_h2   = sym(g_h2);
    float* p_h2r  = sym(g_h2r);
    float* p_wf   = sym(g_wf);
    float* p_hid  = sym(g_hid);
    float* p_Wp   = sym(g_Wp);
    float* p_bp   = sym(g_bp);
    float* p_win  = sym(g_w_in);
    float* p_ws2i = sym(g_w_s2i);
    float* p_wout = sym(g_w_out);
    float* p_we1  = sym(g_w_e1);
    float* p_we2  = sym(g_w_e2);
    int*   p_idx  = symi(g_idx);
    int*   p_cnt  = symi(g_cnt);

    cudaFuncSetAttribute(gemm_tf32<0>, cudaFuncAttributeMaxDynamicSharedMemorySize, SMEM_BYTES);
    cudaFuncSetAttribute(gemm_tf32<1>, cudaFuncAttributeMaxDynamicSharedMemorySize, SMEM_BYTES);
    cudaFuncSetAttribute(gemm_tf32<2>, cudaFuncAttributeMaxDynamicSharedMemorySize, SMEM_BYTES);
    cudaFuncSetAttribute(gemm_tf32<5>, cudaFuncAttributeMaxDynamicSharedMemorySize, SMEM_BYTES);
    cudaFuncSetAttribute(gemm_tf32<6>, cudaFuncAttributeMaxDynamicSharedMemorySize, SMEM_BYTES);

    // 0. weight prep: pack dt/B/C; round all GEMM B weights
    pack_w_kernel<<<(INNER*256)/256, 256>>>(dt_w, bp_w, cp_w, dt_b, bp_b, cp_b, p_Wp, p_bp);
    round_kernel<<<(DD*2*INNER/4 + 255)/256, 256>>>(in_proj_w, p_win, DD*2*INNER/4);
    round_kernel<<<(DSTATE*INNER/4 + 255)/256, 256>>>(s2i_w, p_ws2i, DSTATE*INNER/4);
    round_kernel<<<(INNER*DD/4 + 255)/256, 256>>>(out_w, p_wout, INNER*DD/4);
    round_kernel<<<(EE*DD*HID/4 + 255)/256, 256>>>(e_w1, p_we1, EE*DD*HID/4);
    round_kernel<<<(EE*HID*DD/4 + 255)/256, 256>>>(e_w2, p_we2, EE*HID*DD/4);

    // 1. rmsnorm(x) -> h (rounded)
    rmsnorm_kernel<<<MM, 256>>>(x, norm1_w, p_h, nullptr);

    // 2. xz = h @ in_proj_w + b  [4096,4096] K=1024
    gemm_tf32<0><<<dim3(2*INNER/128, MM/128), 256, SMEM_BYTES>>>(p_h, p_win, p_xz,
        MM, 2*INNER, DD, in_proj_b, nullptr, nullptr, nullptr, 0, nullptr, nullptr);

    // 3. conv + silu -> x_main (exact + rounded)
    conv_silu_kernel<<<(MM*INNER)/256, 256>>>(p_xz, conv_w, conv_b, p_xm, p_xmr);

    // 4. P = xmr @ Wp + bp  [4096,256] K=2048
    gemm_tf32<0><<<dim3(256/128, MM/128), 256, SMEM_BYTES>>>(p_xmr, p_Wp, p_P,
        MM, 256, INNER, p_bp, nullptr, nullptr, nullptr, 0, nullptr, nullptr);

    // 5. selective scan -> y
    scan_kernel<<<BB*DSTATE, 256>>>(p_P, p_y);

    // 6. layernorm over 64 (rounded output)
    ln64_kernel<<<MM, 64>>>(p_y);

    // 7. y2 = (y @ s2i_w + b + D*xm) * sigmoid(gate), rounded  K=64
    gemm_tf32<1><<<dim3(INNER/128, MM/128), 256, SMEM_BYTES>>>(p_y, p_ws2i, p_y2,
        MM, INNER, DSTATE, s2i_b, p_xm, D_param, p_xz + INNER, 2*INNER, nullptr, nullptr);

    // 8. x1 = x + (y2 @ out_w + b), dual-stored to x1 AND d_out  K=2048
    gemm_tf32<2><<<dim3(DD/128, MM/128), 256, SMEM_BYTES>>>(p_y2, p_wout, p_x1,
        MM, DD, INNER, out_b, x, out, nullptr, DD, nullptr, nullptr);

    // 9. rmsnorm(x1) -> h2r (rounded, GEMM) + h2 (exact, gating)
    rmsnorm_kernel<<<MM, 256>>>(p_x1, norm2_w, p_h2r, p_h2);

    // 10. gating (exact h2) -> wf ; compaction -> idx/cnt
    gate_kernel<<<MM, 128>>>(p_h2, gate_w, gate_b, p_wf);
    compact_kernel<<<EE, 256>>>(p_wf, p_idx, p_cnt);

    // 11. per-expert compacted MoE (accumulates into d_out)
    for (int e = 0; e < EE; e++){
        gemm_tf32<5><<<dim3(HID/128, MM/128), 256, SMEM_BYTES>>>(p_h2r, p_we1 + (size_t)e*DD*HID, p_hid,
            MM, HID, DD, e_b1 + (size_t)e*HID, nullptr, nullptr, nullptr, 0,
            p_idx + (size_t)e*MM, p_cnt + e);
        gemm_tf32<6><<<dim3(DD/128, MM/128), 256, SMEM_BYTES>>>(p_hid, p_we2 + (size_t)e*HID*DD, out,
            MM, DD, HID, e_b2 + (size_t)e*DD, p_wf + e, nullptr, nullptr, 0,
            p_idx + (size_t)e*MM, p_cnt + e);
    }
}